// round 3
// baseline (speedup 1.0000x reference)
#include <cuda_runtime.h>

// -------- Instant-NGP constants --------
#define NLEV 16
#define TSZ  (1u << 19)
#define HMASK (TSZ - 1u)
#define P2 2654435761u
#define P3 805459861u

// SMEM weight layout (float offsets)
#define OFF_DW1 0      // 32*64 = 2048
#define OFF_DB1 2048   // 64
#define OFF_DW2 2112   // 64*16 = 1024
#define OFF_DB2 3136   // 16
#define OFF_CW1 3152   // 43*64 = 2752
#define OFF_CB1 5904   // 64
#define OFF_CW2 5968   // 64*64 = 4096
#define OFF_CB2 10064  // 64
#define OFF_CW3 10128  // 64*3 = 192
#define OFF_CB3 10320  // 3
#define W_PAD   10324  // padded total (16B aligned)
#define ACT_FLOATS (64 * 128)
#define SMEM_FLOATS (W_PAD + ACT_FLOATS)
#define SMEM_BYTES  (SMEM_FLOATS * 4)

__global__ void __launch_bounds__(128)
ngp_fused_kernel(const float* __restrict__ x,
                 const float* __restrict__ rdir,
                 const float* __restrict__ tables,
                 const float* __restrict__ dW1, const float* __restrict__ db1,
                 const float* __restrict__ dW2, const float* __restrict__ db2,
                 const float* __restrict__ cW1, const float* __restrict__ cb1,
                 const float* __restrict__ cW2, const float* __restrict__ cb2,
                 const float* __restrict__ cW3, const float* __restrict__ cb3,
                 float* __restrict__ out, int P)
{
    extern __shared__ float sm[];
    float* sW = sm;
    const int tid = threadIdx.x;

    // ---- stage weights into SMEM (broadcast source for all threads) ----
    {
        for (int i = tid; i < 2048; i += 128) sW[OFF_DW1 + i] = dW1[i];
        for (int i = tid; i < 64;   i += 128) sW[OFF_DB1 + i] = db1[i];
        for (int i = tid; i < 1024; i += 128) sW[OFF_DW2 + i] = dW2[i];
        for (int i = tid; i < 16;   i += 128) sW[OFF_DB2 + i] = db2[i];
        for (int i = tid; i < 2752; i += 128) sW[OFF_CW1 + i] = cW1[i];
        for (int i = tid; i < 64;   i += 128) sW[OFF_CB1 + i] = cb1[i];
        for (int i = tid; i < 4096; i += 128) sW[OFF_CW2 + i] = cW2[i];
        for (int i = tid; i < 64;   i += 128) sW[OFF_CB2 + i] = cb2[i];
        for (int i = tid; i < 192;  i += 128) sW[OFF_CW3 + i] = cW3[i];
        for (int i = tid; i < 3;    i += 128) sW[OFF_CB3 + i] = cb3[i];
    }
    __syncthreads();

    const int p = blockIdx.x * 128 + tid;
    if (p >= P) return;                      // full blocks in practice

    // per-thread activation column: sA[k*128] is activation k of this point
    float* sA = sm + W_PAD + tid;

    // ---- load position, mask ----
    const float xf0 = x[3 * p + 0] + 0.5f;
    const float xf1 = x[3 * p + 1] + 0.5f;
    const float xf2 = x[3 * p + 2] + 0.5f;
    const bool inside = (xf0 > 0.f) & (xf0 < 1.f) &
                        (xf1 > 0.f) & (xf1 < 1.f) &
                        (xf2 > 0.f) & (xf2 < 1.f);

    // ---- 16-level hash encoding -> feats into sA[0..31] ----
    // geomspace(16,2048,16).astype(int)
    const float LVL[NLEV] = {16.f, 22.f, 30.f, 42.f, 58.f, 80.f, 111.f, 153.f,
                             212.f, 294.f, 406.f, 561.f, 776.f, 1072.f, 1482.f, 2048.f};
    const float2* __restrict__ tab2 = (const float2*)tables;
#pragma unroll
    for (int l = 0; l < NLEV; l++) {
        const float R = LVL[l];
        const float px = xf0 * R, py = xf1 * R, pz = xf2 * R;
        const float fx = floorf(px), fy = floorf(py), fz = floorf(pz);
        const float frx = px - fx, fry = py - fy, frz = pz - fz;
        const unsigned ux0 = (unsigned)(int)fx;
        const unsigned ux1 = (unsigned)(int)ceilf(px);
        const unsigned uy0 = (unsigned)(int)fy        * P2;
        const unsigned uy1 = (unsigned)(int)ceilf(py) * P2;
        const unsigned uz0 = (unsigned)(int)fz        * P3;
        const unsigned uz1 = (unsigned)(int)ceilf(pz) * P3;
        const float wx0 = 1.f - frx, wy0 = 1.f - fry, wz0 = 1.f - frz;
        const float2* __restrict__ tl = tab2 + (size_t)l * TSZ;
        float ax = 0.f, ay = 0.f;
#pragma unroll
        for (int c = 0; c < 8; c++) {
            unsigned h = ((c & 1) ? ux1 : ux0) ^ ((c & 2) ? uy1 : uy0) ^
                         ((c & 4) ? uz1 : uz0);
            h &= HMASK;
            const float2 v = __ldg(&tl[h]);
            const float w = ((c & 1) ? frx : wx0) * ((c & 2) ? fry : wy0) *
                            ((c & 4) ? frz : wz0);
            ax = fmaf(w, v.x, ax);
            ay = fmaf(w, v.y, ay);
        }
        sA[(2 * l + 0) * 128] = ax;
        sA[(2 * l + 1) * 128] = ay;
    }

    // ---- density layer 1: h1[64] = relu(feats @ dW1 + db1) ----
    float acc[64];
#pragma unroll
    for (int j = 0; j < 16; j++) {
        const float4 b = *(const float4*)(sW + OFF_DB1 + 4 * j);
        acc[4 * j + 0] = b.x; acc[4 * j + 1] = b.y;
        acc[4 * j + 2] = b.z; acc[4 * j + 3] = b.w;
    }
#pragma unroll 2
    for (int k = 0; k < 32; k++) {
        const float a = sA[k * 128];
        const float4* __restrict__ w = (const float4*)(sW + OFF_DW1 + k * 64);
#pragma unroll
        for (int j = 0; j < 16; j++) {
            const float4 wv = w[j];
            acc[4 * j + 0] = fmaf(a, wv.x, acc[4 * j + 0]);
            acc[4 * j + 1] = fmaf(a, wv.y, acc[4 * j + 1]);
            acc[4 * j + 2] = fmaf(a, wv.z, acc[4 * j + 2]);
            acc[4 * j + 3] = fmaf(a, wv.w, acc[4 * j + 3]);
        }
    }
#pragma unroll
    for (int j = 0; j < 64; j++) sA[j * 128] = fmaxf(acc[j], 0.f);

    // ---- density layer 2: log_sigma[16] = h1 @ dW2 + db2 ----
    float ls[16];
#pragma unroll
    for (int j = 0; j < 4; j++) {
        const float4 b = *(const float4*)(sW + OFF_DB2 + 4 * j);
        ls[4 * j + 0] = b.x; ls[4 * j + 1] = b.y;
        ls[4 * j + 2] = b.z; ls[4 * j + 3] = b.w;
    }
#pragma unroll 2
    for (int k = 0; k < 64; k++) {
        const float a = sA[k * 128];
        const float4* __restrict__ w = (const float4*)(sW + OFF_DW2 + k * 16);
#pragma unroll
        for (int j = 0; j < 4; j++) {
            const float4 wv = w[j];
            ls[4 * j + 0] = fmaf(a, wv.x, ls[4 * j + 0]);
            ls[4 * j + 1] = fmaf(a, wv.y, ls[4 * j + 1]);
            ls[4 * j + 2] = fmaf(a, wv.z, ls[4 * j + 2]);
            ls[4 * j + 3] = fmaf(a, wv.w, ls[4 * j + 3]);
        }
    }
    const float ls0 = ls[0];

    // ---- build color-MLP input cin[43] = [log_sigma(16), rd(3), PE(24)] ----
#pragma unroll
    for (int k = 0; k < 16; k++) sA[k * 128] = ls[k];
    const float r0 = rdir[3 * p + 0];
    const float r1 = rdir[3 * p + 1];
    const float r2 = rdir[3 * p + 2];
    sA[16 * 128] = r0; sA[17 * 128] = r1; sA[18 * 128] = r2;
    {
        const float rv[3] = {r0, r1, r2};
#pragma unroll
        for (int d = 0; d < 3; d++) {
#pragma unroll
            for (int l = 0; l < 4; l++) {
                float s, c;
                sincosf(rv[d] * (6.283185307179586f * (float)(1 << l)), &s, &c);
                sA[(19 + d * 8 + l) * 128]     = s;
                sA[(19 + d * 8 + 4 + l) * 128] = c;
            }
        }
    }

    // ---- color layer 1: h[64] = relu(cin @ cW1 + cb1) ----
#pragma unroll
    for (int j = 0; j < 16; j++) {
        const float4 b = *(const float4*)(sW + OFF_CB1 + 4 * j);
        acc[4 * j + 0] = b.x; acc[4 * j + 1] = b.y;
        acc[4 * j + 2] = b.z; acc[4 * j + 3] = b.w;
    }
#pragma unroll 2
    for (int k = 0; k < 43; k++) {
        const float a = sA[k * 128];
        const float4* __restrict__ w = (const float4*)(sW + OFF_CW1 + k * 64);
#pragma unroll
        for (int j = 0; j < 16; j++) {
            const float4 wv = w[j];
            acc[4 * j + 0] = fmaf(a, wv.x, acc[4 * j + 0]);
            acc[4 * j + 1] = fmaf(a, wv.y, acc[4 * j + 1]);
            acc[4 * j + 2] = fmaf(a, wv.z, acc[4 * j + 2]);
            acc[4 * j + 3] = fmaf(a, wv.w, acc[4 * j + 3]);
        }
    }
#pragma unroll
    for (int j = 0; j < 64; j++) sA[j * 128] = fmaxf(acc[j], 0.f);

    // ---- color layer 2: h2[64] = relu(h @ cW2 + cb2) (relu fused below) ----
#pragma unroll
    for (int j = 0; j < 16; j++) {
        const float4 b = *(const float4*)(sW + OFF_CB2 + 4 * j);
        acc[4 * j + 0] = b.x; acc[4 * j + 1] = b.y;
        acc[4 * j + 2] = b.z; acc[4 * j + 3] = b.w;
    }
#pragma unroll 2
    for (int k = 0; k < 64; k++) {
        const float a = sA[k * 128];
        const float4* __restrict__ w = (const float4*)(sW + OFF_CW2 + k * 64);
#pragma unroll
        for (int j = 0; j < 16; j++) {
            const float4 wv = w[j];
            acc[4 * j + 0] = fmaf(a, wv.x, acc[4 * j + 0]);
            acc[4 * j + 1] = fmaf(a, wv.y, acc[4 * j + 1]);
            acc[4 * j + 2] = fmaf(a, wv.z, acc[4 * j + 2]);
            acc[4 * j + 3] = fmaf(a, wv.w, acc[4 * j + 3]);
        }
    }

    // ---- color layer 3 fused: color = sigmoid(relu(h2) @ cW3 + cb3) ----
    float c0 = sW[OFF_CB3 + 0], c1 = sW[OFF_CB3 + 1], c2 = sW[OFF_CB3 + 2];
#pragma unroll
    for (int j = 0; j < 64; j++) {
        const float v = fmaxf(acc[j], 0.f);
        c0 = fmaf(v, sW[OFF_CW3 + j * 3 + 0], c0);
        c1 = fmaf(v, sW[OFF_CW3 + j * 3 + 1], c1);
        c2 = fmaf(v, sW[OFF_CW3 + j * 3 + 2], c2);
    }

    float o0 = 1.f / (1.f + expf(-c0));
    float o1 = 1.f / (1.f + expf(-c1));
    float o2 = 1.f / (1.f + expf(-c2));
    float sg = expf(ls0);
    if (!inside) { o0 = 0.f; o1 = 0.f; o2 = 0.f; sg = 0.f; }

    out[3 * p + 0] = o0;
    out[3 * p + 1] = o1;
    out[3 * p + 2] = o2;
    out[3 * P + p] = sg;   // sigma block after the color block
}

extern "C" void kernel_launch(void* const* d_in, const int* in_sizes, int n_in,
                              void* d_out, int out_size)
{
    (void)n_in; (void)out_size;
    const float* x      = (const float*)d_in[0];
    const float* rdir   = (const float*)d_in[1];
    const float* tables = (const float*)d_in[2];
    const float* dW1    = (const float*)d_in[3];
    const float* db1    = (const float*)d_in[4];
    const float* dW2    = (const float*)d_in[5];
    const float* db2    = (const float*)d_in[6];
    const float* cW1    = (const float*)d_in[7];
    const float* cb1    = (const float*)d_in[8];
    const float* cW2    = (const float*)d_in[9];
    const float* cb2    = (const float*)d_in[10];
    const float* cW3    = (const float*)d_in[11];
    const float* cb3    = (const float*)d_in[12];
    float* out = (float*)d_out;

    const int P = in_sizes[0] / 3;          // 2048*192 = 393216
    const int blocks = (P + 127) / 128;

    cudaFuncSetAttribute(ngp_fused_kernel,
                         cudaFuncAttributeMaxDynamicSharedMemorySize, SMEM_BYTES);
    ngp_fused_kernel<<<blocks, 128, SMEM_BYTES>>>(
        x, rdir, tables, dW1, db1, dW2, db2,
        cW1, cb1, cW2, cb2, cW3, cb3, out, P);
}

// round 5
// speedup vs baseline: 1.2870x; 1.2870x over previous
#include <cuda_runtime.h>

// -------- Instant-NGP constants --------
#define NLEV 16
#define TSZ  (1u << 19)
#define HMASK (TSZ - 1u)
#define P2 2654435761u
#define P3 805459861u

// SMEM weight layout (float offsets) — weights only, activations live in registers
#define OFF_DW1 0      // 32*64 = 2048
#define OFF_DB1 2048   // 64
#define OFF_DW2 2112   // 64*16 = 1024
#define OFF_DB2 3136   // 16
#define OFF_CW1 3152   // 43*64 = 2752
#define OFF_CB1 5904   // 64
#define OFF_CW2 5968   // 64*64 = 4096
#define OFF_CB2 10064  // 64
#define OFF_CW3 10128  // 64*3 = 192
#define OFF_CB3 10320  // 3
#define W_PAD   10324  // 41,296 bytes < 48KB static smem

__global__ void __launch_bounds__(128, 3)
ngp_fused_kernel(const float* __restrict__ x,
                 const float* __restrict__ rdir,
                 const float* __restrict__ tables,
                 const float* __restrict__ dW1, const float* __restrict__ db1,
                 const float* __restrict__ dW2, const float* __restrict__ db2,
                 const float* __restrict__ cW1, const float* __restrict__ cb1,
                 const float* __restrict__ cW2, const float* __restrict__ cb2,
                 const float* __restrict__ cW3, const float* __restrict__ cb3,
                 float* __restrict__ out, int P)
{
    __shared__ float sW[W_PAD];
    const int tid = threadIdx.x;

    // ---- stage weights into SMEM (broadcast source for all threads) ----
    {
        for (int i = tid; i < 2048; i += 128) sW[OFF_DW1 + i] = dW1[i];
        for (int i = tid; i < 64;   i += 128) sW[OFF_DB1 + i] = db1[i];
        for (int i = tid; i < 1024; i += 128) sW[OFF_DW2 + i] = dW2[i];
        for (int i = tid; i < 16;   i += 128) sW[OFF_DB2 + i] = db2[i];
        for (int i = tid; i < 2752; i += 128) sW[OFF_CW1 + i] = cW1[i];
        for (int i = tid; i < 64;   i += 128) sW[OFF_CB1 + i] = cb1[i];
        for (int i = tid; i < 4096; i += 128) sW[OFF_CW2 + i] = cW2[i];
        for (int i = tid; i < 64;   i += 128) sW[OFF_CB2 + i] = cb2[i];
        for (int i = tid; i < 192;  i += 128) sW[OFF_CW3 + i] = cW3[i];
        for (int i = tid; i < 3;    i += 128) sW[OFF_CB3 + i] = cb3[i];
    }
    __syncthreads();

    const int p = blockIdx.x * 128 + tid;
    if (p >= P) return;

    // ---- load position, mask ----
    const float xf0 = x[3 * p + 0] + 0.5f;
    const float xf1 = x[3 * p + 1] + 0.5f;
    const float xf2 = x[3 * p + 2] + 0.5f;
    const bool inside = (xf0 > 0.f) & (xf0 < 1.f) &
                        (xf1 > 0.f) & (xf1 < 1.f) &
                        (xf2 > 0.f) & (xf2 < 1.f);

    // ---- 16-level hash encoding -> feats[32] in REGISTERS ----
    // Masked-out points skip the gathers entirely (their output is zeroed
    // anyway); this removes ~25% of the dominant L1tex wavefront traffic.
    float feats[32];
#pragma unroll
    for (int i = 0; i < 32; i++) feats[i] = 0.f;

    if (inside) {
        const float LVL[NLEV] = {16.f, 22.f, 30.f, 42.f, 58.f, 80.f, 111.f, 153.f,
                                 212.f, 294.f, 406.f, 561.f, 776.f, 1072.f, 1482.f, 2048.f};
        const float2* __restrict__ tab2 = (const float2*)tables;
#pragma unroll
        for (int l = 0; l < NLEV; l++) {
            const float R = LVL[l];
            const float px = xf0 * R, py = xf1 * R, pz = xf2 * R;
            const float fx = floorf(px), fy = floorf(py), fz = floorf(pz);
            const float frx = px - fx, fry = py - fy, frz = pz - fz;
            const unsigned ux0 = (unsigned)(int)fx;
            const unsigned ux1 = (unsigned)(int)ceilf(px);
            const unsigned uy0 = (unsigned)(int)fy        * P2;
            const unsigned uy1 = (unsigned)(int)ceilf(py) * P2;
            const unsigned uz0 = (unsigned)(int)fz        * P3;
            const unsigned uz1 = (unsigned)(int)ceilf(pz) * P3;
            const float wx0 = 1.f - frx, wy0 = 1.f - fry, wz0 = 1.f - frz;
            const float2* __restrict__ tl = tab2 + (size_t)l * TSZ;
            float ax = 0.f, ay = 0.f;
#pragma unroll
            for (int c = 0; c < 8; c++) {
                unsigned h = ((c & 1) ? ux1 : ux0) ^ ((c & 2) ? uy1 : uy0) ^
                             ((c & 4) ? uz1 : uz0);
                h &= HMASK;
                const float2 v = __ldg(&tl[h]);
                const float w = ((c & 1) ? frx : wx0) * ((c & 2) ? fry : wy0) *
                                ((c & 4) ? frz : wz0);
                ax = fmaf(w, v.x, ax);
                ay = fmaf(w, v.y, ay);
            }
            feats[2 * l + 0] = ax;
            feats[2 * l + 1] = ay;
        }
    }

    // ---- density layer 1: h1[64] = relu(feats @ dW1 + db1), j-blocked by 32 ----
    float h1[64];
#pragma unroll
    for (int jb = 0; jb < 2; jb++) {
        float acc[32];
#pragma unroll
        for (int j = 0; j < 8; j++) {
            const float4 b = *(const float4*)(sW + OFF_DB1 + jb * 32 + 4 * j);
            acc[4 * j + 0] = b.x; acc[4 * j + 1] = b.y;
            acc[4 * j + 2] = b.z; acc[4 * j + 3] = b.w;
        }
#pragma unroll
        for (int k = 0; k < 32; k++) {
            const float a = feats[k];
            const float4* __restrict__ w = (const float4*)(sW + OFF_DW1 + k * 64 + jb * 32);
#pragma unroll
            for (int j = 0; j < 8; j++) {
                const float4 wv = w[j];
                acc[4 * j + 0] = fmaf(a, wv.x, acc[4 * j + 0]);
                acc[4 * j + 1] = fmaf(a, wv.y, acc[4 * j + 1]);
                acc[4 * j + 2] = fmaf(a, wv.z, acc[4 * j + 2]);
                acc[4 * j + 3] = fmaf(a, wv.w, acc[4 * j + 3]);
            }
        }
#pragma unroll
        for (int j = 0; j < 32; j++) h1[jb * 32 + j] = fmaxf(acc[j], 0.f);
    }

    // ---- density layer 2: ls[16] = h1 @ dW2 + db2 ----
    float ls[16];
#pragma unroll
    for (int j = 0; j < 4; j++) {
        const float4 b = *(const float4*)(sW + OFF_DB2 + 4 * j);
        ls[4 * j + 0] = b.x; ls[4 * j + 1] = b.y;
        ls[4 * j + 2] = b.z; ls[4 * j + 3] = b.w;
    }
#pragma unroll
    for (int k = 0; k < 64; k++) {
        const float a = h1[k];
        const float4* __restrict__ w = (const float4*)(sW + OFF_DW2 + k * 16);
#pragma unroll
        for (int j = 0; j < 4; j++) {
            const float4 wv = w[j];
            ls[4 * j + 0] = fmaf(a, wv.x, ls[4 * j + 0]);
            ls[4 * j + 1] = fmaf(a, wv.y, ls[4 * j + 1]);
            ls[4 * j + 2] = fmaf(a, wv.z, ls[4 * j + 2]);
            ls[4 * j + 3] = fmaf(a, wv.w, ls[4 * j + 3]);
        }
    }
    const float ls0 = ls[0];

    // ---- color-MLP input cin[43] = [log_sigma(16), rd(3), PE(24)] in registers ----
    float cin[43];
#pragma unroll
    for (int k = 0; k < 16; k++) cin[k] = ls[k];
    {
        const float r0 = rdir[3 * p + 0];
        const float r1 = rdir[3 * p + 1];
        const float r2 = rdir[3 * p + 2];
        cin[16] = r0; cin[17] = r1; cin[18] = r2;
        const float rv[3] = {r0, r1, r2};
#pragma unroll
        for (int d = 0; d < 3; d++) {
#pragma unroll
            for (int l = 0; l < 4; l++) {
                float s, c;
                __sincosf(rv[d] * (6.283185307179586f * (float)(1 << l)), &s, &c);
                cin[19 + d * 8 + l]     = s;
                cin[19 + d * 8 + 4 + l] = c;
            }
        }
    }

    // ---- color layer 1: h[64] = relu(cin @ cW1 + cb1), j-blocked by 32 ----
    float h[64];
#pragma unroll
    for (int jb = 0; jb < 2; jb++) {
        float acc[32];
#pragma unroll
        for (int j = 0; j < 8; j++) {
            const float4 b = *(const float4*)(sW + OFF_CB1 + jb * 32 + 4 * j);
            acc[4 * j + 0] = b.x; acc[4 * j + 1] = b.y;
            acc[4 * j + 2] = b.z; acc[4 * j + 3] = b.w;
        }
#pragma unroll
        for (int k = 0; k < 43; k++) {
            const float a = cin[k];
            const float4* __restrict__ w = (const float4*)(sW + OFF_CW1 + k * 64 + jb * 32);
#pragma unroll
            for (int j = 0; j < 8; j++) {
                const float4 wv = w[j];
                acc[4 * j + 0] = fmaf(a, wv.x, acc[4 * j + 0]);
                acc[4 * j + 1] = fmaf(a, wv.y, acc[4 * j + 1]);
                acc[4 * j + 2] = fmaf(a, wv.z, acc[4 * j + 2]);
                acc[4 * j + 3] = fmaf(a, wv.w, acc[4 * j + 3]);
            }
        }
#pragma unroll
        for (int j = 0; j < 32; j++) h[jb * 32 + j] = fmaxf(acc[j], 0.f);
    }

    // ---- color layers 2+3 fused: c = cb3 + relu(h @ cW2 + cb2) @ cW3 ----
    float c0 = sW[OFF_CB3 + 0], c1 = sW[OFF_CB3 + 1], c2 = sW[OFF_CB3 + 2];
#pragma unroll
    for (int jb = 0; jb < 2; jb++) {
        float acc[32];
#pragma unroll
        for (int j = 0; j < 8; j++) {
            const float4 b = *(const float4*)(sW + OFF_CB2 + jb * 32 + 4 * j);
            acc[4 * j + 0] = b.x; acc[4 * j + 1] = b.y;
            acc[4 * j + 2] = b.z; acc[4 * j + 3] = b.w;
        }
#pragma unroll
        for (int k = 0; k < 64; k++) {
            const float a = h[k];
            const float4* __restrict__ w = (const float4*)(sW + OFF_CW2 + k * 64 + jb * 32);
#pragma unroll
            for (int j = 0; j < 8; j++) {
                const float4 wv = w[j];
                acc[4 * j + 0] = fmaf(a, wv.x, acc[4 * j + 0]);
                acc[4 * j + 1] = fmaf(a, wv.y, acc[4 * j + 1]);
                acc[4 * j + 2] = fmaf(a, wv.z, acc[4 * j + 2]);
                acc[4 * j + 3] = fmaf(a, wv.w, acc[4 * j + 3]);
            }
        }
        // immediately fold this half of h2 into the 3 color logits
#pragma unroll
        for (int j = 0; j < 32; j++) {
            const float v = fmaxf(acc[j], 0.f);
            const int idx = jb * 32 + j;
            c0 = fmaf(v, sW[OFF_CW3 + idx * 3 + 0], c0);
            c1 = fmaf(v, sW[OFF_CW3 + idx * 3 + 1], c1);
            c2 = fmaf(v, sW[OFF_CW3 + idx * 3 + 2], c2);
        }
    }

    float o0 = 1.f / (1.f + __expf(-c0));
    float o1 = 1.f / (1.f + __expf(-c1));
    float o2 = 1.f / (1.f + __expf(-c2));
    float sg = __expf(ls0);
    if (!inside) { o0 = 0.f; o1 = 0.f; o2 = 0.f; sg = 0.f; }

    out[3 * p + 0] = o0;
    out[3 * p + 1] = o1;
    out[3 * p + 2] = o2;
    out[3 * P + p] = sg;   // sigma block after the color block
}

extern "C" void kernel_launch(void* const* d_in, const int* in_sizes, int n_in,
                              void* d_out, int out_size)
{
    (void)n_in; (void)out_size;
    const float* x      = (const float*)d_in[0];
    const float* rdir   = (const float*)d_in[1];
    const float* tables = (const float*)d_in[2];
    const float* dW1    = (const float*)d_in[3];
    const float* db1    = (const float*)d_in[4];
    const float* dW2    = (const float*)d_in[5];
    const float* db2    = (const float*)d_in[6];
    const float* cW1    = (const float*)d_in[7];
    const float* cb1    = (const float*)d_in[8];
    const float* cW2    = (const float*)d_in[9];
    const float* cb2    = (const float*)d_in[10];
    const float* cW3    = (const float*)d_in[11];
    const float* cb3    = (const float*)d_in[12];
    float* out = (float*)d_out;

    const int P = in_sizes[0] / 3;          // 2048*192 = 393216
    const int blocks = (P + 127) / 128;

    ngp_fused_kernel<<<blocks, 128>>>(
        x, rdir, tables, dW1, db1, dW2, db2,
        cW1, cb1, cW2, cb2, cW3, cb3, out, P);
}